// round 3
// baseline (speedup 1.0000x reference)
#include <cuda_runtime.h>
#include <cuda_bf16.h>

// Scratch: per-cell winner (boxIdx+1; 0 = empty). Static zero-init.
// Pass 2 resets every touched cell back to 0, so the buffer is all-zero at
// the start of every kernel_launch call (graph-replay safe, deterministic).
#define MAX_CELLS (4096 * 4096)
__device__ int g_winner[MAX_CELLS];

// Pass 1: per box — winner election for sizemap + 3x3 gaussian scatter-max.
__global__ void __launch_bounds__(256)
heat_scatter_kernel(const float4* __restrict__ boxes,
                    const float* __restrict__ mount,
                    const int* __restrict__ wp,
                    const int* __restrict__ hp,
                    float* __restrict__ out,
                    int n_boxes) {
    int i = blockIdx.x * blockDim.x + threadIdx.x;
    if (i >= n_boxes) return;

    const int w = *wp;
    const int h = *hp;

    float4 b = boxes[i];
    int cx = (int)(b.x * (float)w);
    int cy = (int)(b.y * (float)h);

    // OOB guard (matches JAX scatter-drop semantics; protects g_winner bounds)
    if (cx < 0 || cx >= w || cy < 0 || cy >= h) return;

    // Sizemap winner election: highest box index wins (== sequential last-write)
    atomicMax(&g_winner[cy * w + cx], i + 1);

    // Heatmap: stamp only if the full 3x3 window fits (reference's valid mask)
    if (cx >= 1 && cx <= w - 2 && cy >= 1 && cy <= h - 2) {
        // mount is tiny (9 floats) -> warp-broadcast loads from L1
        float m0 = mount[0], m1 = mount[1], m2 = mount[2];
        float m3 = mount[3], m4 = mount[4], m5 = mount[5];
        float m6 = mount[6], m7 = mount[7], m8 = mount[8];

        // scatter-max via int atomicMax: all values >= 0, heat zero-initialized,
        // so integer ordering of the bit patterns == float ordering.
        int* heat = (int*)out;  // heatmap occupies out[0 : h*w]
        int r0 = (cy - 1) * w + cx;
        int r1 = cy * w + cx;
        int r2 = (cy + 1) * w + cx;
        atomicMax(&heat[r0 - 1], __float_as_int(m0));
        atomicMax(&heat[r0    ], __float_as_int(m1));
        atomicMax(&heat[r0 + 1], __float_as_int(m2));
        atomicMax(&heat[r1 - 1], __float_as_int(m3));
        atomicMax(&heat[r1    ], __float_as_int(m4));
        atomicMax(&heat[r1 + 1], __float_as_int(m5));
        atomicMax(&heat[r2 - 1], __float_as_int(m6));
        atomicMax(&heat[r2    ], __float_as_int(m7));
        atomicMax(&heat[r2 + 1], __float_as_int(m8));
    }
}

// Pass 2: the winning box writes both sizemap channels, then resets its
// winner cell to 0 (restores scratch to the all-zero state for next call).
__global__ void __launch_bounds__(256)
size_write_kernel(const float4* __restrict__ boxes,
                  const int* __restrict__ wp,
                  const int* __restrict__ hp,
                  float* __restrict__ out,
                  int n_boxes) {
    int i = blockIdx.x * blockDim.x + threadIdx.x;
    if (i >= n_boxes) return;

    const int w = *wp;
    const int h = *hp;

    float4 b = boxes[i];
    int cx = (int)(b.x * (float)w);
    int cy = (int)(b.y * (float)h);
    if (cx < 0 || cx >= w || cy < 0 || cy >= h) return;

    int cell = cy * w + cx;
    if (g_winner[cell] == i + 1) {
        int hw = w * h;
        out[hw + cell]     = b.z;  // sizemap channel 0 (box w)
        out[2 * hw + cell] = b.w;  // sizemap channel 1 (box h)
        g_winner[cell] = 0;        // self-reset scratch
    }
}

extern "C" void kernel_launch(void* const* d_in, const int* in_sizes, int n_in,
                              void* d_out, int out_size) {
    const float4* boxes = (const float4*)d_in[0];  // [N,4] cx,cy,w,h
    const float*  mount = (const float*)d_in[1];   // [3,3]
    const int*    wp    = (const int*)d_in[2];     // scalar w
    const int*    hp    = (const int*)d_in[3];     // scalar h
    float* out = (float*)d_out;                    // [h*w heat | h*w size0 | h*w size1]

    int n_boxes = in_sizes[0] / 4;

    // Zero the whole output (heatmap + sizemap). Capturable memset node.
    cudaMemsetAsync(d_out, 0, (size_t)out_size * sizeof(float), 0);

    const int threads = 256;
    int blocks = (n_boxes + threads - 1) / threads;
    heat_scatter_kernel<<<blocks, threads>>>(boxes, mount, wp, hp, out, n_boxes);
    size_write_kernel<<<blocks, threads>>>(boxes, wp, hp, out, n_boxes);
}

// round 4
// speedup vs baseline: 1.0348x; 1.0348x over previous
#include <cuda_runtime.h>
#include <cuda_bf16.h>

// Scratch: per-cell winner (boxIdx+1; 0 = empty). Static zero-init.
// size_write resets every touched cell back to 0, so the buffer is all-zero
// at the start of every call / graph replay (deterministic).
#define MAX_CELLS (4096 * 4096)
__device__ int g_winner[MAX_CELLS];

#define BOX_BATCH 4

// Winner election only — no dependency on any memset, runs overlapped with them.
__global__ void __launch_bounds__(256)
elect_kernel(const float4* __restrict__ boxes,
             const int* __restrict__ wp,
             const int* __restrict__ hp,
             int n_boxes) {
    int base = (blockIdx.x * blockDim.x + threadIdx.x) * BOX_BATCH;
    const int w = *wp;
    const int h = *hp;

    float4 b[BOX_BATCH];
#pragma unroll
    for (int k = 0; k < BOX_BATCH; k++)
        if (base + k < n_boxes) b[k] = __ldg(&boxes[base + k]);

#pragma unroll
    for (int k = 0; k < BOX_BATCH; k++) {
        int i = base + k;
        if (i >= n_boxes) continue;
        int cx = (int)(b[k].x * (float)w);
        int cy = (int)(b[k].y * (float)h);
        if (cx < 0 || cx >= w || cy < 0 || cy >= h) continue;
        atomicMax(&g_winner[cy * w + cx], i + 1);  // no return -> REDG
    }
}

// 3x3 gaussian scatter-max into the heat region (needs heat memset done).
__global__ void __launch_bounds__(256)
heat_scatter_kernel(const float4* __restrict__ boxes,
                    const float* __restrict__ mount,
                    const int* __restrict__ wp,
                    const int* __restrict__ hp,
                    float* __restrict__ out,
                    int n_boxes) {
    int i = blockIdx.x * blockDim.x + threadIdx.x;
    if (i >= n_boxes) return;

    const int w = *wp;
    const int h = *hp;

    float4 b = __ldg(&boxes[i]);
    int cx = (int)(b.x * (float)w);
    int cy = (int)(b.y * (float)h);

    // Stamp only if the full 3x3 window fits (reference's valid mask)
    if (cx >= 1 && cx <= w - 2 && cy >= 1 && cy <= h - 2) {
        float m0 = __ldg(&mount[0]), m1 = __ldg(&mount[1]), m2 = __ldg(&mount[2]);
        float m3 = __ldg(&mount[3]), m4 = __ldg(&mount[4]), m5 = __ldg(&mount[5]);
        float m6 = __ldg(&mount[6]), m7 = __ldg(&mount[7]), m8 = __ldg(&mount[8]);

        // int atomicMax == float max here: all values >= 0, heat zero-initialized.
        int* heat = (int*)out;
        int r0 = (cy - 1) * w + cx;
        int r1 = cy * w + cx;
        int r2 = (cy + 1) * w + cx;
        atomicMax(&heat[r0 - 1], __float_as_int(m0));
        atomicMax(&heat[r0    ], __float_as_int(m1));
        atomicMax(&heat[r0 + 1], __float_as_int(m2));
        atomicMax(&heat[r1 - 1], __float_as_int(m3));
        atomicMax(&heat[r1    ], __float_as_int(m4));
        atomicMax(&heat[r1 + 1], __float_as_int(m5));
        atomicMax(&heat[r2 - 1], __float_as_int(m6));
        atomicMax(&heat[r2    ], __float_as_int(m7));
        atomicMax(&heat[r2 + 1], __float_as_int(m8));
    }
}

// Winner writes both sizemap channels, then resets its winner cell to 0.
// Batched 4 boxes/thread: 4 independent g_winner loads in flight (MLP=4).
__global__ void __launch_bounds__(256)
size_write_kernel(const float4* __restrict__ boxes,
                  const int* __restrict__ wp,
                  const int* __restrict__ hp,
                  float* __restrict__ out,
                  int n_boxes) {
    int base = (blockIdx.x * blockDim.x + threadIdx.x) * BOX_BATCH;
    const int w = *wp;
    const int h = *hp;
    const int hw = w * h;

    float4 b[BOX_BATCH];
    int cell[BOX_BATCH];
    bool ok[BOX_BATCH];
    int win[BOX_BATCH];

#pragma unroll
    for (int k = 0; k < BOX_BATCH; k++) {
        int i = base + k;
        ok[k] = false;
        cell[k] = 0;
        if (i < n_boxes) {
            b[k] = __ldg(&boxes[i]);
            int cx = (int)(b[k].x * (float)w);
            int cy = (int)(b[k].y * (float)h);
            if (cx >= 0 && cx < w && cy >= 0 && cy < h) {
                ok[k] = true;
                cell[k] = cy * w + cx;
            }
        }
    }
#pragma unroll
    for (int k = 0; k < BOX_BATCH; k++)
        win[k] = ok[k] ? g_winner[cell[k]] : 0;

#pragma unroll
    for (int k = 0; k < BOX_BATCH; k++) {
        int i = base + k;
        if (ok[k] && win[k] == i + 1) {
            out[hw + cell[k]]     = b[k].z;  // sizemap channel 0
            out[2 * hw + cell[k]] = b[k].w;  // sizemap channel 1
            g_winner[cell[k]] = 0;           // self-reset scratch
        }
    }
}

extern "C" void kernel_launch(void* const* d_in, const int* in_sizes, int n_in,
                              void* d_out, int out_size) {
    const float4* boxes = (const float4*)d_in[0];  // [N,4] cx,cy,w,h
    const float*  mount = (const float*)d_in[1];   // [3,3]
    const int*    wp    = (const int*)d_in[2];     // scalar w
    const int*    hp    = (const int*)d_in[3];     // scalar h
    float* out = (float*)d_out;                    // [hw heat | hw size0 | hw size1]

    int n_boxes = in_sizes[0] / 4;
    size_t cells = (size_t)out_size / 3;           // h*w, derived host-side
    size_t heat_bytes = cells * sizeof(float);

    // One-time resources (handles only; no device memory allocated here).
    static cudaStream_t sA = []() {
        cudaStream_t s; cudaStreamCreateWithFlags(&s, cudaStreamNonBlocking); return s;
    }();
    static cudaStream_t sB = []() {
        cudaStream_t s; cudaStreamCreateWithFlags(&s, cudaStreamNonBlocking); return s;
    }();
    static cudaEvent_t eRoot = []() {
        cudaEvent_t e; cudaEventCreateWithFlags(&e, cudaEventDisableTiming); return e;
    }();
    static cudaEvent_t eElect = []() {
        cudaEvent_t e; cudaEventCreateWithFlags(&e, cudaEventDisableTiming); return e;
    }();
    static cudaEvent_t eJoinA = []() {
        cudaEvent_t e; cudaEventCreateWithFlags(&e, cudaEventDisableTiming); return e;
    }();

    const int threads = 256;
    int blocks1   = (n_boxes + threads - 1) / threads;
    int n_batched = (n_boxes + BOX_BATCH - 1) / BOX_BATCH;
    int blocksB   = (n_batched + threads - 1) / threads;

    // ---- fork from the capture stream ----
    cudaEventRecord(eRoot, 0);
    cudaStreamWaitEvent(sB, eRoot, 0);
    cudaStreamWaitEvent(sA, eRoot, 0);

    // sB: winner election (independent of all memsets)
    elect_kernel<<<blocksB, threads, 0, sB>>>(boxes, wp, hp, n_boxes);
    cudaEventRecord(eElect, sB);

    // sA: sizemap memset (128 MB) -> wait election -> size writes
    cudaMemsetAsync(out + cells, 0, 2 * heat_bytes, sA);
    cudaStreamWaitEvent(sA, eElect, 0);
    size_write_kernel<<<blocksB, threads, 0, sA>>>(boxes, wp, hp, out, n_boxes);
    cudaEventRecord(eJoinA, sA);

    // s0 (capture stream): heat memset (64 MB) -> gaussian scatter-max
    cudaMemsetAsync(out, 0, heat_bytes, 0);
    heat_scatter_kernel<<<blocks1, threads>>>(boxes, mount, wp, hp, out, n_boxes);

    // ---- join everything back into the capture stream ----
    cudaStreamWaitEvent(0, eElect, 0);   // joins sB
    cudaStreamWaitEvent(0, eJoinA, 0);   // joins sA
}

// round 5
// speedup vs baseline: 1.2661x; 1.2236x over previous
#include <cuda_runtime.h>
#include <cuda_bf16.h>

#define TS 64                    // tile side (pixels)
#define MAX_TILES 4096           // (4096/64)^2
#define BIN_CAP 1000000          // worst case: every box in 4 tiles = 800k

__device__ int g_counts[MAX_TILES];
__device__ int g_offsets[MAX_TILES];
__device__ int g_cursor[MAX_TILES];
__device__ int g_bins[BIN_CAP];

// ---------------- zero counters (fresh every call) ----------------
__global__ void zero_kernel() {
    int i = blockIdx.x * blockDim.x + threadIdx.x;
    if (i < MAX_TILES) { g_counts[i] = 0; g_cursor[i] = 0; }
}

// ---------------- pass 1: count boxes per tile ----------------
__global__ void __launch_bounds__(256)
count_kernel(const float4* __restrict__ boxes,
             const int* __restrict__ wp, const int* __restrict__ hp,
             int n_boxes) {
    int i = blockIdx.x * blockDim.x + threadIdx.x;
    if (i >= n_boxes) return;
    const int w = *wp, h = *hp;
    const int tw = (w + TS - 1) / TS;

    float4 b = __ldg(&boxes[i]);
    int cx = (int)(b.x * (float)w);
    int cy = (int)(b.y * (float)h);
    if (cx < 0 || cx >= w || cy < 0 || cy >= h) return;

    bool valid = (cx >= 1) & (cx <= w - 2) & (cy >= 1) & (cy <= h - 2);
    if (!valid) {
        atomicAdd(&g_counts[(cy / TS) * tw + (cx / TS)], 1);
    } else {
        int tx0 = (cx - 1) / TS, tx1 = (cx + 1) / TS;
        int ty0 = (cy - 1) / TS, ty1 = (cy + 1) / TS;
        for (int ty = ty0; ty <= ty1; ty++)
            for (int tx = tx0; tx <= tx1; tx++)
                atomicAdd(&g_counts[ty * tw + tx], 1);
    }
}

// ---------------- pass 2: exclusive prefix scan (1 CTA, 256 thr) ----------------
__global__ void __launch_bounds__(256)
prefix_kernel() {
    __shared__ int part[256];
    int t = threadIdx.x;
    int base = t * (MAX_TILES / 256);           // 16 tiles per thread
    int local[MAX_TILES / 256];
    int sum = 0;
#pragma unroll
    for (int j = 0; j < MAX_TILES / 256; j++) {
        local[j] = g_counts[base + j];
        sum += local[j];
    }
    part[t] = sum;
    __syncthreads();
    // inclusive log-step scan over the 256 partials
    for (int d = 1; d < 256; d <<= 1) {
        int v = (t >= d) ? part[t - d] : 0;
        __syncthreads();
        part[t] += v;
        __syncthreads();
    }
    int run = part[t] - sum;                    // exclusive prefix for this thread
#pragma unroll
    for (int j = 0; j < MAX_TILES / 256; j++) {
        g_offsets[base + j] = run;
        run += local[j];
    }
}

// ---------------- pass 3: scatter box indices into bins ----------------
__global__ void __launch_bounds__(256)
scatter_kernel(const float4* __restrict__ boxes,
               const int* __restrict__ wp, const int* __restrict__ hp,
               int n_boxes) {
    int i = blockIdx.x * blockDim.x + threadIdx.x;
    if (i >= n_boxes) return;
    const int w = *wp, h = *hp;
    const int tw = (w + TS - 1) / TS;

    float4 b = __ldg(&boxes[i]);
    int cx = (int)(b.x * (float)w);
    int cy = (int)(b.y * (float)h);
    if (cx < 0 || cx >= w || cy < 0 || cy >= h) return;

    bool valid = (cx >= 1) & (cx <= w - 2) & (cy >= 1) & (cy <= h - 2);
    if (!valid) {
        int t = (cy / TS) * tw + (cx / TS);
        g_bins[g_offsets[t] + atomicAdd(&g_cursor[t], 1)] = i;
    } else {
        int tx0 = (cx - 1) / TS, tx1 = (cx + 1) / TS;
        int ty0 = (cy - 1) / TS, ty1 = (cy + 1) / TS;
        for (int ty = ty0; ty <= ty1; ty++)
            for (int tx = tx0; tx <= tx1; tx++) {
                int t = ty * tw + tx;
                g_bins[g_offsets[t] + atomicAdd(&g_cursor[t], 1)] = i;
            }
    }
}

// ---------------- pass 4: per-tile SMEM composite + streamed output ----------------
// One CTA per tile. Fuses zero-fill + scatter-max + sizemap write: the 201 MB
// output is written exactly once, no global atomics, no memset.
__global__ void __launch_bounds__(256)
paint_kernel(const float4* __restrict__ boxes,
             const float* __restrict__ mount,
             const int* __restrict__ wp, const int* __restrict__ hp,
             float* __restrict__ out) {
    __shared__ int s_heat[TS * TS];   // float bits; atomicMax(int) == float max (vals >= 0)
    __shared__ int s_win[TS * TS];    // winner = boxIdx+1 (0 = empty)

    const int w = *wp, h = *hp;
    const int tw = (w + TS - 1) / TS, th = (h + TS - 1) / TS;
    const int ntiles = tw * th;
    const int hw = w * h;

    float m[9];
#pragma unroll
    for (int j = 0; j < 9; j++) m[j] = __ldg(&mount[j]);

    for (int t = blockIdx.x; t < ntiles; t += gridDim.x) {
        for (int k = threadIdx.x; k < TS * TS; k += 256) { s_heat[k] = 0; s_win[k] = 0; }
        __syncthreads();

        const int ty = t / tw, tx = t % tw;
        const int x0 = tx * TS, y0 = ty * TS;
        const int cnt = g_counts[t], off = g_offsets[t];

        for (int j = threadIdx.x; j < cnt; j += 256) {
            int i = g_bins[off + j];
            float4 b = __ldg(&boxes[i]);
            int cx = (int)(b.x * (float)w);
            int cy = (int)(b.y * (float)h);

            // sizemap winner election (center cell in this tile only)
            if (cx / TS == tx && cy / TS == ty)
                atomicMax(&s_win[(cy - y0) * TS + (cx - x0)], i + 1);

            // 3x3 gaussian stamp (only when full window fits in the image)
            if (cx >= 1 && cx <= w - 2 && cy >= 1 && cy <= h - 2) {
#pragma unroll
                for (int dy = -1; dy <= 1; dy++) {
                    int gy = cy + dy - y0;
                    if (gy < 0 || gy >= TS) continue;
#pragma unroll
                    for (int dx = -1; dx <= 1; dx++) {
                        int gx = cx + dx - x0;
                        if (gx < 0 || gx >= TS) continue;
                        atomicMax(&s_heat[gy * TS + gx],
                                  __float_as_int(m[(dy + 1) * 3 + (dx + 1)]));
                    }
                }
            }
        }
        __syncthreads();

        // stream the tile: heat + size0 + size1, float4 coalesced
        for (int idx = threadIdx.x; idx < TS * TS / 4; idx += 256) {
            int row = idx / (TS / 4);
            int c4  = idx % (TS / 4);
            int gy  = y0 + row;
            int gxb = x0 + c4 * 4;
            int soff = row * TS + c4 * 4;

            float4 hv = make_float4(__int_as_float(s_heat[soff + 0]),
                                    __int_as_float(s_heat[soff + 1]),
                                    __int_as_float(s_heat[soff + 2]),
                                    __int_as_float(s_heat[soff + 3]));
            float4 s0 = make_float4(0.f, 0.f, 0.f, 0.f);
            float4 s1 = make_float4(0.f, 0.f, 0.f, 0.f);
#pragma unroll
            for (int q = 0; q < 4; q++) {
                int wv = s_win[soff + q];
                if (wv > 0) {
                    float4 bb = __ldg(&boxes[wv - 1]);
                    ((float*)&s0)[q] = bb.z;
                    ((float*)&s1)[q] = bb.w;
                }
            }
            if (gy < h && gxb + 3 < w) {
                int g = gy * w + gxb;
                *(float4*)(out + g)          = hv;
                *(float4*)(out + hw + g)     = s0;
                *(float4*)(out + 2 * hw + g) = s1;
            } else {
#pragma unroll
                for (int q = 0; q < 4; q++) {
                    int gx = gxb + q;
                    if (gy < h && gx < w) {
                        int g = gy * w + gx;
                        out[g]          = ((float*)&hv)[q];
                        out[hw + g]     = ((float*)&s0)[q];
                        out[2 * hw + g] = ((float*)&s1)[q];
                    }
                }
            }
        }
        __syncthreads();   // protect smem re-zero of next tile iteration
    }
}

extern "C" void kernel_launch(void* const* d_in, const int* in_sizes, int n_in,
                              void* d_out, int out_size) {
    const float4* boxes = (const float4*)d_in[0];  // [N,4] cx,cy,w,h
    const float*  mount = (const float*)d_in[1];   // [3,3]
    const int*    wp    = (const int*)d_in[2];     // scalar w
    const int*    hp    = (const int*)d_in[3];     // scalar h
    float* out = (float*)d_out;                    // [hw heat | hw size0 | hw size1]

    int n_boxes = in_sizes[0] / 4;

    const int threads = 256;
    int bblocks = (n_boxes + threads - 1) / threads;

    zero_kernel<<<(MAX_TILES + threads - 1) / threads, threads>>>();
    count_kernel<<<bblocks, threads>>>(boxes, wp, hp, n_boxes);
    prefix_kernel<<<1, threads>>>();
    scatter_kernel<<<bblocks, threads>>>(boxes, wp, hp, n_boxes);
    paint_kernel<<<MAX_TILES, threads>>>(boxes, mount, wp, hp, out);
}